// round 10
// baseline (speedup 1.0000x reference)
#include <cuda_runtime.h>
#include <cstddef>
#include <cstdint>

#define D        128
#define TWO_D    256
#define MAX_NODES 50000

// Scratch: P[n][0:128] = src projection, P[n][128:256] = dst projection.
__device__ float g_P[(size_t)MAX_NODES * TWO_D];

// L2 evict_last policy handle (per-thread, cheap).
__device__ __forceinline__ uint64_t mk_evict_last() {
    uint64_t pol;
    asm("createpolicy.fractional.L2::evict_last.b64 %0, 1.0;" : "=l"(pol));
    return pol;
}

// Read-only float4 load with L2 evict_last cache hint (pins P against the
// streaming e_out writes).
__device__ __forceinline__ float4 ldg_el(const float4* p, uint64_t pol) {
    float4 v;
    asm("ld.global.nc.L2::cache_hint.v4.f32 {%0,%1,%2,%3}, [%4], %5;"
        : "=f"(v.x), "=f"(v.y), "=f"(v.z), "=f"(v.w) : "l"(p), "l"(pol));
    return v;
}

// ---------------------------------------------------------------------------
// Kernel 1: node projection GEMM.  P[n][off+j] = sum_k n_f[n][k] * We[j][off+k]
// TM=128, TN=128 (off = blockIdx.y*128 picks the src/dst half of W_edge's
// input dim). K chunked by 16, DOUBLE-BUFFERED: prefetch chunk c+1 into regs,
// compute chunk c, store regs to the other buffer, one sync per chunk.
// 256 threads, 8x8 microtile, 4x LDS.128 per k, conflict-free phases.
// ---------------------------------------------------------------------------
__global__ __launch_bounds__(256) void proj_kernel(
    const float* __restrict__ nf,
    const float* __restrict__ We,
    int n_nodes)
{
    __shared__ float As[2][16][132];   // [buf][k_local][row], pad 4
    __shared__ float Bs[2][16][132];   // [buf][k_local][col]

    const int t    = threadIdx.x;
    const int tx   = t & 15;
    const int ty   = t >> 4;
    const int row0 = blockIdx.x * 128;
    const int off  = blockIdx.y * D;

    // Per-thread load coords: 512 float4 per tile-chunk, 2 per thread.
    int lr[2], lc4[2];
#pragma unroll
    for (int i = 0; i < 2; i++) { int idx = t + i * 256; lr[i] = idx >> 2; lc4[i] = idx & 3; }

    float acc[8][8];
#pragma unroll
    for (int i = 0; i < 8; i++)
#pragma unroll
        for (int j = 0; j < 8; j++) acc[i][j] = 0.f;

    // Load chunk 0 into buffer 0.
#pragma unroll
    for (int i = 0; i < 2; i++) {
        int gr = row0 + lr[i];
        float4 va = make_float4(0.f, 0.f, 0.f, 0.f);
        if (gr < n_nodes)
            va = __ldg((const float4*)(nf + (size_t)gr * D) + lc4[i]);
        int k = lc4[i] * 4;
        As[0][k + 0][lr[i]] = va.x; As[0][k + 1][lr[i]] = va.y;
        As[0][k + 2][lr[i]] = va.z; As[0][k + 3][lr[i]] = va.w;
        float4 vb = __ldg((const float4*)(We + (size_t)lr[i] * TWO_D + off) + lc4[i]);
        Bs[0][k + 0][lr[i]] = vb.x; Bs[0][k + 1][lr[i]] = vb.y;
        Bs[0][k + 2][lr[i]] = vb.z; Bs[0][k + 3][lr[i]] = vb.w;
    }
    __syncthreads();

    const int NCH = D / 16;   // 8 chunks
    for (int c = 0; c < NCH; c++) {
        const int buf = c & 1;

        // Prefetch chunk c+1 into registers (LDG latency overlapped w/ compute).
        float4 pa[2], pb[2];
        if (c + 1 < NCH) {
            int kc = (c + 1) * 16;
#pragma unroll
            for (int i = 0; i < 2; i++) {
                int gr = row0 + lr[i];
                pa[i] = make_float4(0.f, 0.f, 0.f, 0.f);
                if (gr < n_nodes)
                    pa[i] = __ldg((const float4*)(nf + (size_t)gr * D + kc) + lc4[i]);
                pb[i] = __ldg((const float4*)(We + (size_t)lr[i] * TWO_D + off + kc) + lc4[i]);
            }
        }

#pragma unroll
        for (int k = 0; k < 16; k++) {
            float av[8], bv[8];
            *(float4*)&av[0] = *(const float4*)&As[buf][k][ty * 4];
            *(float4*)&av[4] = *(const float4*)&As[buf][k][64 + ty * 4];
            *(float4*)&bv[0] = *(const float4*)&Bs[buf][k][tx * 4];
            *(float4*)&bv[4] = *(const float4*)&Bs[buf][k][64 + tx * 4];
#pragma unroll
            for (int i = 0; i < 8; i++)
#pragma unroll
                for (int j = 0; j < 8; j++)
                    acc[i][j] = fmaf(av[i], bv[j], acc[i][j]);
        }

        if (c + 1 < NCH) {
            const int nb = buf ^ 1;
#pragma unroll
            for (int i = 0; i < 2; i++) {
                int k = lc4[i] * 4;
                As[nb][k + 0][lr[i]] = pa[i].x; As[nb][k + 1][lr[i]] = pa[i].y;
                As[nb][k + 2][lr[i]] = pa[i].z; As[nb][k + 3][lr[i]] = pa[i].w;
                Bs[nb][k + 0][lr[i]] = pb[i].x; Bs[nb][k + 1][lr[i]] = pb[i].y;
                Bs[nb][k + 2][lr[i]] = pb[i].z; Bs[nb][k + 3][lr[i]] = pb[i].w;
            }
        }
        __syncthreads();
    }

#pragma unroll
    for (int half = 0; half < 2; half++) {
#pragma unroll
        for (int i = 0; i < 4; i++) {
            int gr = row0 + half * 64 + ty * 4 + i;
            if (gr < n_nodes) {
                int ai = half * 4 + i;
                float* p = g_P + (size_t)gr * TWO_D + off;
                *(float4*)(p + tx * 4) =
                    make_float4(acc[ai][0], acc[ai][1], acc[ai][2], acc[ai][3]);
                *(float4*)(p + 64 + tx * 4) =
                    make_float4(acc[ai][4], acc[ai][5], acc[ai][6], acc[ai][7]);
            }
        }
    }
}

// ---------------------------------------------------------------------------
// Kernel 2: per-edge apply, 8 edges per warp -> 16 outstanding 16B gathers
// per thread. P reads carry L2 evict_last cache hints; output stores are
// streaming (evict_first) so the 516 MB write stream can't evict the 51 MB
// L2-resident P table.
// ---------------------------------------------------------------------------
__global__ __launch_bounds__(256) void edge_kernel(
    const int* __restrict__ src,
    const int* __restrict__ dst,
    const float* __restrict__ w_attn,
    float* __restrict__ e_out,
    float* __restrict__ a_out,
    int n_edges)
{
    const int lane = threadIdx.x & 31;
    const int warp = (int)((blockIdx.x * (unsigned)blockDim.x + threadIdx.x) >> 5);
    const int e0   = warp * 8;
    if (e0 >= n_edges) return;
    const int ne = min(8, n_edges - e0);

    const uint64_t pol = mk_evict_last();
    float4 w = __ldg((const float4*)w_attn + lane);

    int s[8], d[8];
#pragma unroll
    for (int i = 0; i < 8; i++) {
        int e = e0 + ((i < ne) ? i : 0);
        s[i] = __ldg(src + e);
        d[i] = __ldg(dst + e);
    }

    float4 a[8], b[8];
#pragma unroll
    for (int i = 0; i < 8; i++) {
        a[i] = ldg_el((const float4*)(g_P + (size_t)s[i] * TWO_D) + lane, pol);
        b[i] = ldg_el((const float4*)(g_P + (size_t)d[i] * TWO_D + D) + lane, pol);
    }

    float dot[8];
#pragma unroll
    for (int i = 0; i < 8; i++) {
        float4 r;
        r.x = fmaxf(a[i].x + b[i].x, 0.f);
        r.y = fmaxf(a[i].y + b[i].y, 0.f);
        r.z = fmaxf(a[i].z + b[i].z, 0.f);
        r.w = fmaxf(a[i].w + b[i].w, 0.f);
        if (i < ne)
            __stcs((float4*)(e_out + (size_t)(e0 + i) * D) + lane, r);
        dot[i] = r.x * w.x + r.y * w.y + r.z * w.z + r.w * w.w;
    }

    // Eight independent butterfly chains, interleaved for ILP.
#pragma unroll
    for (int o = 16; o; o >>= 1) {
#pragma unroll
        for (int i = 0; i < 8; i++)
            dot[i] += __shfl_xor_sync(0xffffffffu, dot[i], o);
    }

    // All lanes hold all eight dots; lanes 0..ne-1 write coalesced.
    float v = dot[0];
#pragma unroll
    for (int i = 1; i < 8; i++)
        if (lane == i) v = dot[i];
    if (lane < ne) {
        v = v > 0.f ? v : 0.01f * v;
        __stcs(a_out + e0 + lane, v);
    }
}

// ---------------------------------------------------------------------------
// Launch. Inputs: n_f [N*128] f32, src_idx [E] i32, dst_idx [E] i32,
// W_edge [128*256] f32, W_attn [128] f32. Output: [e_feat E*128 | a_fact E].
// ---------------------------------------------------------------------------
extern "C" void kernel_launch(void* const* d_in, const int* in_sizes, int n_in,
                              void* d_out, int out_size)
{
    const float* nf  = (const float*)d_in[0];
    const int*   src = (const int*)d_in[1];
    const int*   dst = (const int*)d_in[2];
    const float* We  = (const float*)d_in[3];
    const float* Wa  = (const float*)d_in[4];

    int n_nodes = in_sizes[0] / D;
    if (n_nodes > MAX_NODES) n_nodes = MAX_NODES;
    int n_edges = in_sizes[1];

    float* e_out = (float*)d_out;
    float* a_out = e_out + (size_t)n_edges * D;

    dim3 pgrid((n_nodes + 127) / 128, 2);
    proj_kernel<<<pgrid, 256>>>(nf, We, n_nodes);

    int warps  = (n_edges + 7) / 8;
    int blocks = (warps * 32 + 255) / 256;
    edge_kernel<<<blocks, 256>>>(src, dst, Wa, e_out, a_out, n_edges);
}